// round 17
// baseline (speedup 1.0000x reference)
#include <cuda_runtime.h>

// pred/target: (2,2,128,128,128) fp32 contiguous. idx = bc*2^21 + d*2^14 + h*2^7 + w
#define NTOT 8388608
#define BC_STRIDE 2097152
#define D_STRIDE  16384

// Squared EDT after W+H passes: integer <= 32258 -> u16. 65535 = inf sentinel.
__device__ unsigned short g_p16[NTOT];
__device__ unsigned short g_t16[NTOT];
__device__ double g_acc;
__device__ int g_count;

// ---------------------------------------------------------------------------
// Fused pass1 (W axis, two-sweep + square) + pass2 (H axis, pruned exact scan,
// per-thread exit). One (bc,d) slab 128x128 per block. grid=(512,2), block=256.
// ---------------------------------------------------------------------------
__global__ void __launch_bounds__(256) k_pass12(const float* __restrict__ pred,
                                                const float* __restrict__ target) {
    __shared__ unsigned short dsq[128][130];
    const float* src = blockIdx.y ? target : pred;
    unsigned short* dst = blockIdx.y ? g_t16 : g_p16;
    const int tid = threadIdx.x;
    const long base = (long)blockIdx.x * 16384;

    if (blockIdx.x == 0 && blockIdx.y == 0 && tid == 0) g_acc = 0.0;

    // vectorized mask load: 0 = background, 255 = foreground
    const float4* src4 = (const float4*)(src + base);
    #pragma unroll
    for (int it = 0; it < 16; it++) {
        int idx = it * 256 + tid;            // 0..4095 float4
        float4 v = src4[idx];
        int r  = idx >> 5;                   // 32 float4 per row
        int w4 = (idx & 31) * 4;
        *(ushort2*)&dsq[r][w4]     = make_ushort2(v.x >= 0.5f ? 255 : 0,
                                                  v.y >= 0.5f ? 255 : 0);
        *(ushort2*)&dsq[r][w4 + 2] = make_ushort2(v.z >= 0.5f ? 255 : 0,
                                                  v.w >= 0.5f ? 255 : 0);
    }
    __syncthreads();

    // pass1: forward/backward sweep along w (thread = row h); square folded in.
    if (tid < 128) {
        unsigned short* row = dsq[tid];
        int d = 255;
        #pragma unroll 4
        for (int w = 0; w < 128; w++) {
            d = (row[w] == 0) ? 0 : min(d + 1, 255);
            row[w] = (unsigned short)d;
        }
        int db = 255;
        #pragma unroll 4
        for (int w = 127; w >= 0; w--) {
            int df = row[w];
            db = (df == 0) ? 0 : min(db + 1, 255);
            int m = min(df, db);
            row[w] = (m == 255) ? (unsigned short)65535 : (unsigned short)(m * m);
        }
    }
    __syncthreads();

    // pass2: out[x][w] = min_y (dsq[y][w] + (x-y)^2), pruned outward scan with
    // PER-THREAD exit (SIMT reconvergence = same iteration count as a vote,
    // minus the VOTE instruction on the dependence chain).
    const int warp = tid >> 5, lane = tid & 31;
    for (int i = 0; i < 16; i++) {
        int x = warp + 8 * i;
        #pragma unroll
        for (int wg = 0; wg < 4; wg++) {
            int w = wg * 32 + lane;
            int b = dsq[x][w];
            int rr = 1;
            for (int r = 1; r < 128; r++) {
                if (rr >= b) break;                      // per-thread exit
                int lo = x - r, hi = x + r;
                if (lo >= 0)  b = min(b, (int)dsq[lo][w] + rr);
                if (hi < 128) b = min(b, (int)dsq[hi][w] + rr);
                rr += 2 * r + 1;
            }
            dst[base + x * 128 + w] =
                (b > 32258) ? (unsigned short)65535 : (unsigned short)b;
        }
    }
}

// ---------------------------------------------------------------------------
// Pass3 (D axis, pruned scan with per-thread exit, both tensors) fused with
// the loss reduction + the final scalar (last-block pattern).
// Block = 512, tile = fixed (bc,h), w0..w0+63, all 128 d. grid=(2,128,4).
// ---------------------------------------------------------------------------
__global__ void __launch_bounds__(512) k_pass3(const float* __restrict__ pred,
                                               const float* __restrict__ target,
                                               const int* __restrict__ is_avg,
                                               float* __restrict__ out) {
    __shared__ unsigned short gp[128][66];
    __shared__ unsigned short gt[128][66];
    __shared__ double sd[16];

    const int tid = threadIdx.x;
    const int w0 = blockIdx.x * 64;
    const int h  = blockIdx.y;
    const int bc = blockIdx.z;
    const long base = (long)bc * BC_STRIDE + (long)h * 128 + w0;

    // stage g tiles (coalesced ushort2 loads: 64 u16 = 128B per row)
    #pragma unroll
    for (int it = 0; it < 8; it++) {
        int idx = it * 512 + tid;            // 0..4095 ushort2
        int d = idx >> 5, w2 = (idx & 31) * 2;
        long a = base + (long)d * D_STRIDE + w2;
        *(ushort2*)&gp[d][w2] = *(const ushort2*)&g_p16[a];
        *(ushort2*)&gt[d][w2] = *(const ushort2*)&g_t16[a];
    }
    __syncthreads();

    // pruned scans along d + inline loss (per-thread exit)
    const int warp = tid >> 5, lane = tid & 31;
    double acc = 0.0;
    for (int i = 0; i < 8; i++) {
        int x = warp + 16 * i;
        #pragma unroll
        for (int wg = 0; wg < 2; wg++) {
            int w = wg * 32 + lane;
            int bp = gp[x][w];
            int bt = gt[x][w];
            int rr = 1;
            for (int r = 1; r < 128; r++) {
                if (rr >= max(bp, bt)) break;            // per-thread exit
                int lo = x - r, hi = x + r;
                if (lo >= 0) {
                    bp = min(bp, (int)gp[lo][w] + rr);
                    bt = min(bt, (int)gt[lo][w] + rr);
                }
                if (hi < 128) {
                    bp = min(bp, (int)gp[hi][w] + rr);
                    bt = min(bt, (int)gt[hi][w] + rr);
                }
                rr += 2 * r + 1;
            }
            long a = base + (long)x * D_STRIDE + w;
            float e = pred[a] - target[a];               // coalesced 128B
            acc += (double)(e * e * (float)(bp + bt));   // <= 96774: exact f32
        }
    }

    // warp-shuffle reduce, then cross-warp
    #pragma unroll
    for (int s = 16; s > 0; s >>= 1)
        acc += __shfl_down_sync(0xffffffffu, acc, s);
    if (lane == 0) sd[warp] = acc;
    __syncthreads();
    if (warp == 0) {
        double v = (lane < 16) ? sd[lane] : 0.0;
        #pragma unroll
        for (int s = 8; s > 0; s >>= 1)
            v += __shfl_down_sync(0xffffffffu, v, s);
        if (lane == 0) atomicAdd(&g_acc, v);
    }
    __syncthreads();

    // last block computes the final scalar
    if (tid == 0) {
        __threadfence();
        int old = atomicAdd(&g_count, 1);
        if (old == 2 * 128 * 4 - 1) {
            double m = g_acc / (double)NTOT;
            if (*is_avg == 0) m *= 2.0;      // * pred.shape[0]
            out[0] = (float)m;
            g_count = 0;                      // reset for next graph replay
        }
    }
}

extern "C" void kernel_launch(void* const* d_in, const int* in_sizes, int n_in,
                              void* d_out, int out_size) {
    const float* pred   = (const float*)d_in[0];
    const float* target = (const float*)d_in[1];
    const int*   is_avg = (const int*)d_in[2];
    float* out = (float*)d_out;

    k_pass12<<<dim3(512, 2), 256>>>(pred, target);
    k_pass3<<<dim3(2, 128, 4), 512>>>(pred, target, is_avg, out);
}